// round 6
// baseline (speedup 1.0000x reference)
#include <cuda_runtime.h>
#include <cstdint>
#include <cstddef>

#define T_TOT 8192
#define MULT  512
#define OUTW  8192
#define VROW  1536

#define BT 64
#define BW 128
#define NTHR 512
#define NITER 16

#define PR 40                         // padded words per smem row (A and B)
#define A_STAGE_W (3*BT*PR)           // 7680 words (3 comp planes x 64 rows x 40)
#define B_STAGE_W (BW*PR)             // 5120 words (128 rows x 40)
#define STAGE_W   (A_STAGE_W + B_STAGE_W)   // 12800
#define DYN_SMEM  (2*STAGE_W*4)       // 102400 bytes

#define VPLANE (T_TOT*MULT)           // words per component plane in scratch

// ---- scratch (static device globals: allowed; no runtime allocation)
__device__ uint32_t g_Vd[3u * VPLANE];        // tf32 bits, [i][t][kperm(u)]
__device__ uint32_t g_W1t[MULT * MULT];       // tf32 bits, [n][kperm(u)]

static __device__ __forceinline__ uint32_t smem_u32(const void* p) {
    uint32_t r;
    asm("{ .reg .u64 t; cvta.to.shared.u64 t, %1; cvt.u32.u64 %0, t; }" : "=r"(r) : "l"(p));
    return r;
}
static __device__ __forceinline__ uint32_t f2tf(float x) {
    uint32_t r; asm("cvt.rna.tf32.f32 %0, %1;" : "=r"(r) : "f"(x)); return r;
}
static __device__ __forceinline__ int kperm(int u) {   // (k, k+4) -> adjacent words
    return 8 * (u >> 3) + 2 * (u & 3) + ((u >> 2) & 1);
}
static __device__ __forceinline__ int invkperm(int w) { // inverse of kperm
    return 8 * (w >> 3) + 4 * (w & 1) + ((w >> 1) & 3);
}
static __device__ __forceinline__ void cpa16(uint32_t dst, const void* src) {
    asm volatile("cp.async.cg.shared.global [%0], [%1], 16;" :: "r"(dst), "l"(src));
}
static __device__ __forceinline__ void mma8(float* c, const uint32_t* a, const uint32_t* b) {
    asm volatile(
        "mma.sync.aligned.m16n8k8.row.col.f32.tf32.tf32.f32 "
        "{%0,%1,%2,%3},{%4,%5,%6,%7},{%8,%9},{%0,%1,%2,%3};\n"
        : "+f"(c[0]), "+f"(c[1]), "+f"(c[2]), "+f"(c[3])
        : "r"(a[0]), "r"(a[1]), "r"(a[2]), "r"(a[3]),
          "r"(b[0]), "r"(b[1]));
}

// ---- pre-kernel 1: V [t][3u+i] -> g_Vd[i][t][kperm(u)], tf32-rounded
__global__ void __launch_bounds__(512, 2)
pre_v(const float* __restrict__ V) {
    __shared__ float srow[4 * VROW];           // 4 token rows
    const int tid = threadIdx.x;
    const int r0  = blockIdx.x * 4;
    const float4* v4 = reinterpret_cast<const float4*>(V) + (size_t)r0 * 384;
#pragma unroll
    for (int k = 0; k < 3; k++) {
        const int c = tid + k * 512;           // 0..1535 float4 chunks
        const float4 d = v4[c];
        float* sp = srow + 4 * c;
        sp[0] = d.x; sp[1] = d.y; sp[2] = d.z; sp[3] = d.w;
    }
    __syncthreads();
    const int u = invkperm(tid);               // tid is destination word w
#pragma unroll
    for (int r = 0; r < 4; r++) {
        const float* sp = srow + r * VROW + 3 * u;
        const size_t o = (size_t)(r0 + r) * 512 + tid;
        g_Vd[o]              = f2tf(sp[0]);
        g_Vd[o + VPLANE]     = f2tf(sp[1]);
        g_Vd[o + 2 * VPLANE] = f2tf(sp[2]);
    }
}

// ---- pre-kernel 2: W1 [u][n] -> g_W1t[n][kperm(u)], tf32-rounded
__global__ void __launch_bounds__(256)
pre_w(const float* __restrict__ W1) {
    __shared__ float tile[32][33];
    const int tx = threadIdx.x, ty = threadIdx.y;   // (32, 8)
    const int bu = blockIdx.y * 32, bn = blockIdx.x * 32;
#pragma unroll
    for (int j = 0; j < 32; j += 8)
        tile[ty + j][tx] = W1[(size_t)(bu + ty + j) * MULT + bn + tx];
    __syncthreads();
    const int wloc = kperm(tx);                 // tx = local u, permuted dest
#pragma unroll
    for (int j = 0; j < 32; j += 8)
        g_W1t[(size_t)(bn + ty + j) * MULT + bu + wloc] = f2tf(tile[tx][ty + j]);
}

// ---- main fused kernel
__global__ void __launch_bounds__(NTHR, 1)
fused(const float* __restrict__ S, const float* __restrict__ W0,
      float* __restrict__ out)
{
    extern __shared__ uint32_t dsm[];
    __shared__ float sS[192];
    __shared__ float sW0[384];

    const int tid  = threadIdx.x;
    const int lane = tid & 31;
    const int wid  = tid >> 5;
    const int q  = lane >> 2;          // 0..7
    const int rr = lane & 3;           // 0..3
    const int warp_t = wid >> 2;       // 0..3 -> rows warp_t*16
    const int warp_w = wid & 3;        // 0..3 -> cols warp_w*32
    const int bx = blockIdx.x, by = blockIdx.y;
    const int tt0 = by * BT, w0 = bx * BW;

    if (tid < 192) sS[tid]  = S[(size_t)tt0 * 3 + tid];
    if (tid < 384) sW0[tid] = W0[(tid >> 7) * 512 + w0 + (tid & 127)];

    // ---- cp.async staging addresses (loop-invariant)
    const uint32_t smem0 = smem_u32(dsm);
    uint32_t aDst[3]; const uint32_t* aSrc[3];
#pragma unroll
    for (int s = 0; s < 3; s++) {
        const int c = tid + s * NTHR;          // 0..1535 (3 planes x 64 t x 8 chunks)
        const int i = c >> 9, rem = c & 511;
        const int t = rem >> 3, j = rem & 7;
        aDst[s] = smem0 + (i * (BT * PR) + t * PR + 4 * j) * 4;
        aSrc[s] = g_Vd + (size_t)i * VPLANE + (size_t)(tt0 + t) * 512 + 4 * j;
    }
    uint32_t bDst[2]; const uint32_t* bSrc[2];
#pragma unroll
    for (int s = 0; s < 2; s++) {
        const int c = tid + s * NTHR;          // 0..1023 (128 n x 8 chunks)
        const int n = c >> 3, j = c & 7;
        bDst[s] = smem0 + (A_STAGE_W + n * PR + 4 * j) * 4;
        bSrc[s] = g_W1t + (size_t)(w0 + n) * 512 + 4 * j;
    }

#define STAGE(K, BUF) do {                                                  \
        const uint32_t off_ = (BUF) * (STAGE_W * 4);                        \
        const int kw_ = (K) * 32;                                          \
        _Pragma("unroll")                                                   \
        for (int s_ = 0; s_ < 3; s_++) cpa16(aDst[s_] + off_, aSrc[s_] + kw_); \
        _Pragma("unroll")                                                   \
        for (int s_ = 0; s_ < 2; s_++) cpa16(bDst[s_] + off_, bSrc[s_] + kw_); \
        asm volatile("cp.async.commit_group;" ::: "memory");                \
    } while (0)

    float acc[3][4][4];
#pragma unroll
    for (int i = 0; i < 3; i++)
#pragma unroll
        for (int n = 0; n < 4; n++)
#pragma unroll
            for (int r = 0; r < 4; r++) acc[i][n][r] = 0.f;

    STAGE(0, 0);
    STAGE(1, 1);

    float4* out4 = reinterpret_cast<float4*>(out);
    const float4 zq = make_float4(0.f, 0.f, 0.f, 0.f);

    for (int it = 0; it < NITER; ++it) {
        const int buf = it & 1;
        if (it < NITER - 2) asm volatile("cp.async.wait_group 1;" ::: "memory");
        else                asm volatile("cp.async.wait_group 0;" ::: "memory");
        __syncthreads();

        // ---- stream the exact-zero block (4 rows x 384 quads per iter)
        {
            const int r = 4 * it + (tid >> 7);
            const int c = (tid & 127) * 3;
            float4* zp = out4 + (size_t)(tt0 + r) * 2048 + 512 + 384 * bx + c;
            zp[0] = zq; zp[1] = zq; zp[2] = zq;
        }

        // ---- compute 4 k8-steps: all-LDS.64 fragments, zero cvt
        const uint32_t* sA = dsm + buf * STAGE_W;
        const uint32_t* sB = sA + A_STAGE_W;
        const int arow0 = (warp_t * 16 + q) * PR;
#pragma unroll
        for (int g = 0; g < 4; g++) {
            const int kcol = 8 * g + 2 * rr;
            uint32_t b[4][2];
#pragma unroll
            for (int nt = 0; nt < 4; nt++) {
                const int n = warp_w * 32 + nt * 8 + q;
                const uint2 bb = *reinterpret_cast<const uint2*>(&sB[n * PR + kcol]);
                b[nt][0] = bb.x; b[nt][1] = bb.y;     // k=rr, k=rr+4
            }
#pragma unroll
            for (int i = 0; i < 3; i++) {
                const uint32_t* ap = sA + i * (BT * PR) + arow0 + kcol;
                const uint2 alo = *reinterpret_cast<const uint2*>(ap);            // row q
                const uint2 ahi = *reinterpret_cast<const uint2*>(ap + 8 * PR);   // row q+8
                uint32_t a[4] = {alo.x, ahi.x, alo.y, ahi.y};
#pragma unroll
                for (int nt = 0; nt < 4; nt++) mma8(acc[i][nt], a, b[nt]);
            }
        }
        __syncthreads();
        if (it < NITER - 2) STAGE(it + 2, buf);
    }

    // ---- epilogue: out1 (1o->1o), interleaved layout, vectorized float2
    const float sc = 0.04419417382415922f;  // 1/sqrt(512)
    {
        const int r  = tt0 + warp_t * 16 + q;
        const int wc = w0 + warp_w * 32 + 2 * rr;
#pragma unroll
        for (int nt = 0; nt < 4; nt++) {
            const int w = wc + nt * 8;
            float* p  = out + (size_t)r * OUTW + 512 + 3 * w;
            float* p2 = p + (size_t)8 * OUTW;
            float2 v;
            v = make_float2(acc[0][nt][0] * sc, acc[1][nt][0] * sc); *reinterpret_cast<float2*>(p + 0) = v;
            v = make_float2(acc[2][nt][0] * sc, acc[0][nt][1] * sc); *reinterpret_cast<float2*>(p + 2) = v;
            v = make_float2(acc[1][nt][1] * sc, acc[2][nt][1] * sc); *reinterpret_cast<float2*>(p + 4) = v;
            v = make_float2(acc[0][nt][2] * sc, acc[1][nt][2] * sc); *reinterpret_cast<float2*>(p2 + 0) = v;
            v = make_float2(acc[2][nt][2] * sc, acc[0][nt][3] * sc); *reinterpret_cast<float2*>(p2 + 2) = v;
            v = make_float2(acc[1][nt][3] * sc, acc[2][nt][3] * sc); *reinterpret_cast<float2*>(p2 + 4) = v;
        }
    }

    // ---- epilogue: out0 (0e->0e), cols [w0, w0+128)
    {
        const float k3 = 0.5773502691896258f;  // 1/sqrt(3)
        const int r  = tid >> 3;
        const int cb = (tid & 7) * 16;
        const float s0 = sS[r * 3 + 0], s1 = sS[r * 3 + 1], s2 = sS[r * 3 + 2];
        float* po = out + (size_t)(tt0 + r) * OUTW + w0 + cb;
#pragma unroll
        for (int jj = 0; jj < 16; jj += 4) {
            float4 v;
            v.x = (s0 * sW0[cb + jj + 0] + s1 * sW0[128 + cb + jj + 0] + s2 * sW0[256 + cb + jj + 0]) * k3;
            v.y = (s0 * sW0[cb + jj + 1] + s1 * sW0[128 + cb + jj + 1] + s2 * sW0[256 + cb + jj + 1]) * k3;
            v.z = (s0 * sW0[cb + jj + 2] + s1 * sW0[128 + cb + jj + 2] + s2 * sW0[256 + cb + jj + 2]) * k3;
            v.w = (s0 * sW0[cb + jj + 3] + s1 * sW0[128 + cb + jj + 3] + s2 * sW0[256 + cb + jj + 3]) * k3;
            *reinterpret_cast<float4*>(po + jj) = v;
        }
    }
}

extern "C" void kernel_launch(void* const* d_in, const int* in_sizes, int n_in,
                              void* d_out, int out_size) {
    const float* V  = nullptr;   // vectors [4,2048,1536] = 12582912
    const float* S  = nullptr;   // scalars [4,2048,3]    = 24576
    const float* W0 = nullptr;   // [3,512]               = 1536
    const float* W1 = nullptr;   // [512,512]             = 262144
    for (int i = 0; i < n_in; i++) {
        switch (in_sizes[i]) {
            case 12582912: V  = (const float*)d_in[i]; break;
            case 24576:    S  = (const float*)d_in[i]; break;
            case 1536:     W0 = (const float*)d_in[i]; break;
            case 262144:   W1 = (const float*)d_in[i]; break;
            default: break;
        }
    }
    float* out = (float*)d_out;

    // preprocessing: layout + tf32-round (same stream => ordered, graph-capturable)
    pre_v<<<T_TOT / 4, 512>>>(V);
    pre_w<<<dim3(16, 16), dim3(32, 8)>>>(W1);

    cudaFuncSetAttribute(fused, cudaFuncAttributeMaxDynamicSharedMemorySize, DYN_SMEM);
    dim3 grid(MULT / BW, T_TOT / BT);   // (4, 128) = 512 CTAs
    fused<<<grid, NTHR, DYN_SMEM>>>(S, W0, out);
}

// round 7
// speedup vs baseline: 1.2577x; 1.2577x over previous
#include <cuda_runtime.h>
#include <cstdint>
#include <cstddef>

#define T_TOT 8192
#define MULT  512
#define OUTW  8192
#define VROW  1536

#define BT 32
#define BW 128
#define NTHR 256
#define NITER 16

#define A_STAGE_W (3*BT*32)           // 3072 words (3 planes x 32 rows x 32)
#define B_STAGE_W (BW*32)             // 4096 words
#define STAGE_W   (A_STAGE_W + B_STAGE_W)   // 7168
#define NSTAGE 3
#define DYN_SMEM  (NSTAGE*STAGE_W*4)  // 86016 bytes

#define VPLANE (T_TOT*MULT)

// ---- scratch (static device globals: allowed; no runtime allocation)
__device__ uint32_t g_Vd[3u * VPLANE];        // tf32 bits, [i][t][perm word]
__device__ uint32_t g_W1t[MULT * MULT];       // tf32 bits, [n][perm word]

static __device__ __forceinline__ uint32_t smem_u32(const void* p) {
    uint32_t r;
    asm("{ .reg .u64 t; cvta.to.shared.u64 t, %1; cvt.u32.u64 %0, t; }" : "=r"(r) : "l"(p));
    return r;
}
static __device__ __forceinline__ uint32_t f2tf(float x) {
    uint32_t r; asm("cvt.rna.tf32.f32 %0, %1;" : "=r"(r) : "f"(x)); return r;
}
// conflict-free stored word for logical u (within 32-chunk) at matrix row `row`:
//   u = 8*g + 4*h + c  ->  word = 8*c + 2*((g + row) & 3) + h
static __device__ __forceinline__ int permw(int uu, int row) {
    const int g = uu >> 3, h = (uu >> 2) & 1, c = uu & 3;
    return 8 * c + 2 * ((g + row) & 3) + h;
}
static __device__ __forceinline__ void cpa16(uint32_t dst, const void* src) {
    asm volatile("cp.async.cg.shared.global [%0], [%1], 16;" :: "r"(dst), "l"(src));
}
static __device__ __forceinline__ void mma8(float* c, const uint32_t* a, const uint32_t* b) {
    asm volatile(
        "mma.sync.aligned.m16n8k8.row.col.f32.tf32.tf32.f32 "
        "{%0,%1,%2,%3},{%4,%5,%6,%7},{%8,%9},{%0,%1,%2,%3};\n"
        : "+f"(c[0]), "+f"(c[1]), "+f"(c[2]), "+f"(c[3])
        : "r"(a[0]), "r"(a[1]), "r"(a[2]), "r"(a[3]),
          "r"(b[0]), "r"(b[1]));
}

// ---- pre-kernel 1: V [t][3u+i] -> g_Vd[i][t][chunk*32 + permw(u%32, t)]
__global__ void __launch_bounds__(512, 2)
pre_v(const float* __restrict__ V) {
    __shared__ float srow[4 * VROW];
    const int tid = threadIdx.x;
    const int r0  = blockIdx.x * 4;
    const float4* v4 = reinterpret_cast<const float4*>(V) + (size_t)r0 * 384;
#pragma unroll
    for (int k = 0; k < 3; k++) {
        const int c = tid + k * 512;
        const float4 d = v4[c];
        float* sp = srow + 4 * c;
        sp[0] = d.x; sp[1] = d.y; sp[2] = d.z; sp[3] = d.w;
    }
    __syncthreads();
    const int u   = tid;                 // source k index 0..511
    const int c32 = u >> 5, uu = u & 31;
#pragma unroll
    for (int r = 0; r < 4; r++) {
        const int t = r0 + r;
        const int w = c32 * 32 + permw(uu, t);
        const float* sp = srow + r * VROW + 3 * u;
        const size_t o = (size_t)t * 512 + w;
        g_Vd[o]              = f2tf(sp[0]);
        g_Vd[o + VPLANE]     = f2tf(sp[1]);
        g_Vd[o + 2 * VPLANE] = f2tf(sp[2]);
    }
}

// ---- pre-kernel 2: W1 [u][n] -> g_W1t[n][bu + permw(u%32, n)]
__global__ void __launch_bounds__(256)
pre_w(const float* __restrict__ W1) {
    __shared__ float tile[32][33];
    const int tx = threadIdx.x, ty = threadIdx.y;   // (32, 8)
    const int bu = blockIdx.y * 32, bn = blockIdx.x * 32;
#pragma unroll
    for (int j = 0; j < 32; j += 8)
        tile[ty + j][tx] = W1[(size_t)(bu + ty + j) * MULT + bn + tx];
    __syncthreads();
#pragma unroll
    for (int j = 0; j < 32; j += 8) {
        const int n = bn + ty + j;
        g_W1t[(size_t)n * 512 + bu + permw(tx, n)] = f2tf(tile[tx][ty + j]);
    }
}

// ---- main fused kernel
__global__ void __launch_bounds__(NTHR, 2)
fused(const float* __restrict__ S, const float* __restrict__ W0,
      float* __restrict__ out)
{
    extern __shared__ uint32_t dsm[];
    __shared__ float sS[96];
    __shared__ float sW0[384];

    const int tid  = threadIdx.x;
    const int lane = tid & 31;
    const int wid  = tid >> 5;
    const int q  = lane >> 2;          // 0..7
    const int rr = lane & 3;           // 0..3
    const int warp_t = wid >> 2;       // 0..1 -> rows warp_t*16
    const int warp_w = wid & 3;        // 0..3 -> cols warp_w*32
    const int bx = blockIdx.x, by = blockIdx.y;
    const int tt0 = by * BT, w0 = bx * BW;

    if (tid < 96)  sS[tid]  = S[(size_t)tt0 * 3 + tid];
    if (tid < 256) { sW0[tid] = W0[(tid >> 7) * 512 + w0 + (tid & 127)];
                     if (tid < 128) sW0[256 + tid] = W0[1024 + w0 + tid]; }

    // ---- cp.async staging addresses (loop-invariant)
    const uint32_t smem0 = smem_u32(dsm);
    uint32_t aDst[3]; const uint32_t* aSrc[3];
#pragma unroll
    for (int s = 0; s < 3; s++) {
        const int c = tid + s * NTHR;          // 0..767 (3 planes x 32 t x 8 chunks)
        const int i = c >> 8, rem = c & 255;
        const int t = rem >> 3, j = rem & 7;
        aDst[s] = smem0 + (i * (BT * 32) + t * 32 + 4 * j) * 4;
        aSrc[s] = g_Vd + (size_t)i * VPLANE + (size_t)(tt0 + t) * 512 + 4 * j;
    }
    uint32_t bDst[4]; const uint32_t* bSrc[4];
#pragma unroll
    for (int s = 0; s < 4; s++) {
        const int c = tid + s * NTHR;          // 0..1023 (128 n x 8 chunks)
        const int n = c >> 3, j = c & 7;
        bDst[s] = smem0 + (A_STAGE_W + n * 32 + 4 * j) * 4;
        bSrc[s] = g_W1t + (size_t)(w0 + n) * 512 + 4 * j;
    }

#define STAGE(K, BUF) do {                                                  \
        const uint32_t off_ = (BUF) * (STAGE_W * 4);                        \
        const int kw_ = (K) * 32;                                          \
        _Pragma("unroll")                                                   \
        for (int s_ = 0; s_ < 3; s_++) cpa16(aDst[s_] + off_, aSrc[s_] + kw_); \
        _Pragma("unroll")                                                   \
        for (int s_ = 0; s_ < 4; s_++) cpa16(bDst[s_] + off_, bSrc[s_] + kw_); \
        asm volatile("cp.async.commit_group;" ::: "memory");                \
    } while (0)

    float acc[3][4][4];
#pragma unroll
    for (int i = 0; i < 3; i++)
#pragma unroll
        for (int n = 0; n < 4; n++)
#pragma unroll
            for (int r = 0; r < 4; r++) acc[i][n][r] = 0.f;

    STAGE(0, 0);
    STAGE(1, 1);

    float4* out4 = reinterpret_cast<float4*>(out);
    const float4 zq = make_float4(0.f, 0.f, 0.f, 0.f);

    int buf = 0;
    for (int it = 0; it < NITER; ++it) {
        if (it == NITER - 1) asm volatile("cp.async.wait_group 0;" ::: "memory");
        else                 asm volatile("cp.async.wait_group 1;" ::: "memory");
        __syncthreads();

        if (it + 2 < NITER) {
            const int nb = (buf + 2 >= NSTAGE) ? buf + 2 - NSTAGE : buf + 2;
            STAGE(it + 2, nb);
        }

        // ---- stream the exact-zero block (2 rows x 384 quads per iter)
        {
            const int r = 2 * it + (tid >> 7);
            const int c = (tid & 127) * 3;
            float4* zp = out4 + (size_t)(tt0 + r) * 2048 + 512 + 384 * bx + c;
            zp[0] = zq; zp[1] = zq; zp[2] = zq;
        }

        // ---- compute 4 k8-steps (conflict-free LDS.64 everywhere)
        const uint32_t* sA = dsm + buf * STAGE_W;
        const uint32_t* sB = sA + A_STAGE_W;
        const int arow = (warp_t * 16 + q) * 32;
#pragma unroll
        for (int g = 0; g < 4; g++) {
            const int koff = 8 * rr + 2 * ((g + q) & 3);   // same for A rows & B cols
            uint32_t b[4][2];
#pragma unroll
            for (int nt = 0; nt < 4; nt++) {
                const int n = warp_w * 32 + nt * 8 + q;
                const uint2 bb = *reinterpret_cast<const uint2*>(&sB[n * 32 + koff]);
                b[nt][0] = bb.x; b[nt][1] = bb.y;     // k = 8g+rr, 8g+rr+4
            }
#pragma unroll
            for (int i = 0; i < 3; i++) {
                const uint32_t* ap = sA + i * (BT * 32) + arow + koff;
                const uint2 alo = *reinterpret_cast<const uint2*>(ap);        // row q
                const uint2 ahi = *reinterpret_cast<const uint2*>(ap + 256);  // row q+8
                uint32_t a[4] = {alo.x, ahi.x, alo.y, ahi.y};
#pragma unroll
                for (int nt = 0; nt < 4; nt++) mma8(acc[i][nt], a, b[nt]);
            }
        }
        buf = (buf + 1 >= NSTAGE) ? 0 : buf + 1;
    }

    // ---- epilogue: out1 (1o->1o), interleaved layout, vectorized float2
    const float sc = 0.04419417382415922f;  // 1/sqrt(512)
    {
        const int r  = tt0 + warp_t * 16 + q;
        const int wc = w0 + warp_w * 32 + 2 * rr;
#pragma unroll
        for (int nt = 0; nt < 4; nt++) {
            const int w = wc + nt * 8;
            float* p  = out + (size_t)r * OUTW + 512 + 3 * w;
            float* p2 = p + (size_t)8 * OUTW;
            float2 v;
            v = make_float2(acc[0][nt][0] * sc, acc[1][nt][0] * sc); *reinterpret_cast<float2*>(p + 0) = v;
            v = make_float2(acc[2][nt][0] * sc, acc[0][nt][1] * sc); *reinterpret_cast<float2*>(p + 2) = v;
            v = make_float2(acc[1][nt][1] * sc, acc[2][nt][1] * sc); *reinterpret_cast<float2*>(p + 4) = v;
            v = make_float2(acc[0][nt][2] * sc, acc[1][nt][2] * sc); *reinterpret_cast<float2*>(p2 + 0) = v;
            v = make_float2(acc[2][nt][2] * sc, acc[0][nt][3] * sc); *reinterpret_cast<float2*>(p2 + 2) = v;
            v = make_float2(acc[1][nt][3] * sc, acc[2][nt][3] * sc); *reinterpret_cast<float2*>(p2 + 4) = v;
        }
    }

    // ---- epilogue: out0 (0e->0e), cols [w0, w0+128)
    {
        const float k3 = 0.5773502691896258f;  // 1/sqrt(3)
        const int r  = tid >> 3;               // 0..31
        const int cb = (tid & 7) * 16;
        const float s0 = sS[r * 3 + 0], s1 = sS[r * 3 + 1], s2 = sS[r * 3 + 2];
        float* po = out + (size_t)(tt0 + r) * OUTW + w0 + cb;
#pragma unroll
        for (int jj = 0; jj < 16; jj += 4) {
            float4 v;
            v.x = (s0 * sW0[cb + jj + 0] + s1 * sW0[128 + cb + jj + 0] + s2 * sW0[256 + cb + jj + 0]) * k3;
            v.y = (s0 * sW0[cb + jj + 1] + s1 * sW0[128 + cb + jj + 1] + s2 * sW0[256 + cb + jj + 1]) * k3;
            v.z = (s0 * sW0[cb + jj + 2] + s1 * sW0[128 + cb + jj + 2] + s2 * sW0[256 + cb + jj + 2]) * k3;
            v.w = (s0 * sW0[cb + jj + 3] + s1 * sW0[128 + cb + jj + 3] + s2 * sW0[256 + cb + jj + 3]) * k3;
            *reinterpret_cast<float4*>(po + jj) = v;
        }
    }
}

extern "C" void kernel_launch(void* const* d_in, const int* in_sizes, int n_in,
                              void* d_out, int out_size) {
    const float* V  = nullptr;   // vectors [4,2048,1536] = 12582912
    const float* S  = nullptr;   // scalars [4,2048,3]    = 24576
    const float* W0 = nullptr;   // [3,512]               = 1536
    const float* W1 = nullptr;   // [512,512]             = 262144
    for (int i = 0; i < n_in; i++) {
        switch (in_sizes[i]) {
            case 12582912: V  = (const float*)d_in[i]; break;
            case 24576:    S  = (const float*)d_in[i]; break;
            case 1536:     W0 = (const float*)d_in[i]; break;
            case 262144:   W1 = (const float*)d_in[i]; break;
            default: break;
        }
    }
    float* out = (float*)d_out;

    pre_v<<<T_TOT / 4, 512>>>(V);
    pre_w<<<dim3(16, 16), dim3(32, 8)>>>(W1);

    cudaFuncSetAttribute(fused, cudaFuncAttributeMaxDynamicSharedMemorySize, DYN_SMEM);
    dim3 grid(MULT / BW, T_TOT / BT);   // (4, 256) = 1024 CTAs
    fused<<<grid, NTHR, DYN_SMEM>>>(S, W0, out);
}